// round 12
// baseline (speedup 1.0000x reference)
#include <cuda_runtime.h>
#include <cuda_fp16.h>
#include <math.h>
#include <stdint.h>

// B=4, L=4096, D=1024, H=16, W=256, FF=4096, HD=64, nC=16, M=B*L=16384

// -------- scratch (device globals; no allocation allowed) --------
__device__ __half g_qkvh [16384ull * 3072];
__device__ __half g_xh   [16384ull * 1024];
__device__ __half g_attnh[16384ull * 1024];
__device__ __half g_x1h  [16384ull * 1024];
__device__ __half g_ffnh [16384ull * 4096];
__device__ __half g_tmph [16384ull * 1024];
__device__ __half g_inwh [3072ull * 1024];
__device__ __half g_outwh[1024ull * 1024];
__device__ __half g_w1th [4096ull * 1024];
__device__ __half g_w2th [1024ull * 4096];
__device__ float  g_x1   [16384ull * 1024];

// ======================= helpers =======================
__device__ __forceinline__ uint32_t smem_u32(const void* p) {
    uint32_t a;
    asm("{ .reg .u64 t; cvta.to.shared.u64 t, %1; cvt.u32.u64 %0, t; }"
        : "=r"(a) : "l"(p));
    return a;
}
__device__ __forceinline__ void cp16(uint32_t saddr, const void* g) {
    asm volatile("cp.async.cg.shared.global [%0], [%1], 16;"
                 :: "r"(saddr), "l"(g) : "memory");
}
__device__ __forceinline__ void cp_commit() {
    asm volatile("cp.async.commit_group;" ::: "memory");
}
__device__ __forceinline__ void cp_wait1() {
    asm volatile("cp.async.wait_group 1;" ::: "memory");
}
__device__ __forceinline__ void cp_wait0() {
    asm volatile("cp.async.wait_group 0;" ::: "memory");
}
__device__ __forceinline__ void mma_f16(float* c, const uint32_t* a, const uint32_t* b) {
    asm volatile(
        "mma.sync.aligned.m16n8k16.row.col.f32.f16.f16.f32 "
        "{%0,%1,%2,%3},{%4,%5,%6,%7},{%8,%9},{%0,%1,%2,%3};"
        : "+f"(c[0]), "+f"(c[1]), "+f"(c[2]), "+f"(c[3])
        : "r"(a[0]), "r"(a[1]), "r"(a[2]), "r"(a[3]), "r"(b[0]), "r"(b[1]));
}
#define LDSM_X4(R, addr) \
    asm volatile("ldmatrix.sync.aligned.m8n8.x4.shared.b16 {%0,%1,%2,%3}, [%4];" \
                 : "=r"((R)[0]), "=r"((R)[1]), "=r"((R)[2]), "=r"((R)[3]) : "r"(addr))
#define LDSM_X4_T(R, addr) \
    asm volatile("ldmatrix.sync.aligned.m8n8.x4.trans.shared.b16 {%0,%1,%2,%3}, [%4];" \
                 : "=r"((R)[0]), "=r"((R)[1]), "=r"((R)[2]), "=r"((R)[3]) : "r"(addr))
__device__ __forceinline__ uint32_t packh2(float a, float b) {
    __half2 h = __floats2half2_rn(a, b);
    return *(uint32_t*)&h;
}

// ======================= fp16 mma.sync GEMM =======================
// C[M,N] = Ah[M,K] @ Bth[N,K]^T + bias (optional ReLU, optional fp16 out).
// CTA tile 128(M) x 256(N), BK=64, 512 threads = 16 warps (2M x 8N),
// warp tile 64x32 (identical per-warp code/registers to the R11 kernel).
// 3-stage cp.async; XOR chunk swizzle (chunk ^= row&7), conflict-free for
// cp.async stores and ldmatrix. ONE barrier per iter, issue-after-sync:
// writing stage (kt+2)%3 == (kt-1)%3 is drained once all warps passed the
// iter-kt barrier (compute(kt-1) precedes it in program order).
// Rationale: 256-wide N halves B traffic per output -> per-SM L2 demand
// drops from ~64 B/cyc to ~23 B/cyc, under the ~6.3KB/cyc chip LTS cap.

#define STG_BYTES 49152            // A(16384) + B(32768) per stage
#define GEMM_SMEM (3 * STG_BYTES)  // 147456

template<bool RELU, bool OUTH>
__global__ __launch_bounds__(512)
void hgemm_kernel(const __half* __restrict__ A, const __half* __restrict__ Bt,
                  const float* __restrict__ bias, void* __restrict__ Cv,
                  int N, int K)
{
    extern __shared__ __align__(128) char smem[];
    const uint32_t sb = smem_u32(smem);

    const int tid  = threadIdx.x;
    const int lane = tid & 31;
    const int wid  = tid >> 5;          // 0..15
    const int g = lane >> 2;
    const int t = lane & 3;
    const int wm = (wid & 1) * 64;      // M half
    const int wn = (wid >> 1) * 32;     // N slice (8 x 32)

    const int bm = blockIdx.y * 128;
    const int bn = blockIdx.x * 256;

    // A staging: row = tid>>2 (0..127), 2 chunks; B: row = tid>>1 (0..255), 4 chunks
    const int arow = tid >> 2;
    const int ac0  = (tid & 3) * 2;
    const int brow = tid >> 1;
    const int bc0  = (tid & 1) * 4;
    const __half* Ag = A  + (size_t)(bm + arow) * K + ac0 * 8;
    const __half* Bg = Bt + (size_t)(bn + brow) * K + bc0 * 8;
    uint32_t dstA[2], dstB[4];
#pragma unroll
    for (int i = 0; i < 2; i++)
        dstA[i] = sb + arow * 128 + (((ac0 + i) ^ (arow & 7)) << 4);
#pragma unroll
    for (int i = 0; i < 4; i++)
        dstB[i] = sb + 16384 + brow * 128 + (((bc0 + i) ^ (brow & 7)) << 4);

    const int KT = K >> 6;

    // prologue: stages 0,1
#pragma unroll
    for (int s = 0; s < 2; s++) {
        const uint32_t off = s * STG_BYTES;
        const int k0 = s * 64;
#pragma unroll
        for (int i = 0; i < 2; i++) cp16(dstA[i] + off, Ag + k0 + i * 8);
#pragma unroll
        for (int i = 0; i < 4; i++) cp16(dstB[i] + off, Bg + k0 + i * 8);
        cp_commit();
    }

    float c[16][4];
#pragma unroll
    for (int i = 0; i < 16; i++)
#pragma unroll
        for (int j = 0; j < 4; j++) c[i][j] = 0.f;

    // fragment lane addressing
    const int afr = wm + (lane & 15);
    const int a8  = lane >> 4;
    const int bfr = wn + ((lane >> 4) & 1) * 8 + (lane & 7);
    const int b8  = (lane >> 3) & 1;
    const int fswz = lane & 7;

    int rd = 0, wr = 2;
    for (int kt = 0; kt < KT; kt++) {
        cp_wait1();
        __syncthreads();

        if (kt + 2 < KT) {
            const uint32_t off = wr * STG_BYTES;
            const int k0 = (kt + 2) * 64;
#pragma unroll
            for (int i = 0; i < 2; i++) cp16(dstA[i] + off, Ag + k0 + i * 8);
#pragma unroll
            for (int i = 0; i < 4; i++) cp16(dstB[i] + off, Bg + k0 + i * 8);
            cp_commit();
        }
        wr = (wr == 2) ? 0 : wr + 1;

        const uint32_t sA = sb + rd * STG_BYTES;
        const uint32_t sB = sA + 16384;
        rd = (rd == 2) ? 0 : rd + 1;

#pragma unroll
        for (int kk = 0; kk < 4; kk++) {
            uint32_t a[4][4], kb[2][4];
            const int ca = ((kk * 2 + a8) ^ fswz) << 4;
            const int cb = ((kk * 2 + b8) ^ fswz) << 4;
#pragma unroll
            for (int mt = 0; mt < 4; mt++)
                LDSM_X4(a[mt], sA + (afr + mt * 16) * 128 + ca);
#pragma unroll
            for (int ntp = 0; ntp < 2; ntp++)
                LDSM_X4(kb[ntp], sB + (bfr + ntp * 16) * 128 + cb);
#pragma unroll
            for (int mt = 0; mt < 4; mt++)
#pragma unroll
                for (int nt = 0; nt < 4; nt++)
                    mma_f16(c[mt * 4 + nt], a[mt], &kb[nt >> 1][(nt & 1) * 2]);
        }
    }

    // epilogue
#pragma unroll
    for (int mt = 0; mt < 4; mt++) {
#pragma unroll
        for (int nt = 0; nt < 4; nt++) {
            const float* cc = c[mt * 4 + nt];
            const int row = bm + wm + mt * 16 + g;
            const int col = bn + wn + nt * 8 + 2 * t;
            const float bx = __ldg(bias + col);
            const float by = __ldg(bias + col + 1);
            float v00 = cc[0] + bx, v01 = cc[1] + by;
            float v10 = cc[2] + bx, v11 = cc[3] + by;
            if (RELU) {
                v00 = fmaxf(v00, 0.f); v01 = fmaxf(v01, 0.f);
                v10 = fmaxf(v10, 0.f); v11 = fmaxf(v11, 0.f);
            }
            if (OUTH) {
                __half* C = (__half*)Cv;
                *(__half2*)(C + (size_t)row * N + col)       = __floats2half2_rn(v00, v01);
                *(__half2*)(C + (size_t)(row + 8) * N + col) = __floats2half2_rn(v10, v11);
            } else {
                float* C = (float*)Cv;
                float2 a0; a0.x = v00; a0.y = v01;
                float2 a1; a1.x = v10; a1.y = v11;
                *(float2*)(C + (size_t)row * N + col)       = a0;
                *(float2*)(C + (size_t)(row + 8) * N + col) = a1;
            }
        }
    }
}

// ======================= converters =======================
__global__ __launch_bounds__(256)
void cvt_kernel(const float* __restrict__ in, __half* __restrict__ out, size_t n8)
{
    const size_t i = (size_t)blockIdx.x * 256 + threadIdx.x;
    if (i >= n8) return;
    const float4 u = *(const float4*)(in + i * 8);
    const float4 v = *(const float4*)(in + i * 8 + 4);
    uint4 st;
    st.x = packh2(u.x, u.y); st.y = packh2(u.z, u.w);
    st.z = packh2(v.x, v.y); st.w = packh2(v.z, v.w);
    *(uint4*)(out + i * 8) = st;
}

__global__ __launch_bounds__(256)
void transpose_cvt_kernel(const float* __restrict__ in, __half* __restrict__ out,
                          int R, int C)  // in[R,C] fp32 -> out[C,R] fp16
{
    __shared__ float tbuf[32][33];
    const int tx = threadIdx.x, ty = threadIdx.y;
    const int x = blockIdx.x * 32 + tx;
    const int y0 = blockIdx.y * 32;
#pragma unroll
    for (int j = ty; j < 32; j += 8)
        tbuf[j][tx] = in[(size_t)(y0 + j) * C + x];
    __syncthreads();
    const int ox = y0 + tx;
    const int oy0 = blockIdx.x * 32;
#pragma unroll
    for (int j = ty; j < 32; j += 8)
        out[(size_t)(oy0 + j) * R + ox] = __float2half(tbuf[tx][j]);
}

// ======================= fp16 tensor-core windowed attention =======================
// Double-buffered K/V stages: loads for tile i+1 are issued after the iter-i
// barrier (target stage last read in compute(i-1), drained by the barrier);
// cp_wait0 at iter i+1 covers a group issued one full compute earlier.
#define AQ_STRIDE 72
#define KV_STG (128 * AQ_STRIDE)                       // K(64 rows)+V(64 rows) halves
#define ATTN_SMEM ((256 * AQ_STRIDE + 2 * KV_STG) * 2) // 73728 B

__global__ __launch_bounds__(256, 1)
void attn_kernel(const __half* __restrict__ qkv, __half* __restrict__ out)
{
    extern __shared__ __align__(128) char asmem[];
    const uint32_t sQ = smem_u32(asmem);
    const uint32_t sKV0 = sQ + 256 * AQ_STRIDE * 2;

    const int idx = blockIdx.x;        // b*256 + c*16 + h
    const int h = idx & 15;
    const int c = (idx >> 4) & 15;
    const int b = idx >> 8;
    const int tid = threadIdx.x;
    const int lane = tid & 31;
    const int wid = tid >> 5;
    const int g = lane >> 2;
    const int t = lane & 3;
    const int q0 = wid * 32;

    // ---- stage Q via cp.async ----
    {
        const size_t qtok = (size_t)b * 4096 + (size_t)c * 256 + tid;
        const __half* qp = qkv + qtok * 3072 + h * 64;
        const uint32_t dst = sQ + tid * (AQ_STRIDE * 2);
#pragma unroll
        for (int i = 0; i < 8; i++)
            cp16(dst + i * 16, qp + i * 8);
    }

    const int qfr = q0 + (lane & 15);
    const int qfc = (lane >> 4) * 8;
    const int kfr = ((lane >> 4) & 1) * 8 + (lane & 7);
    const int kfc = ((lane >> 3) & 1) * 8;
    const int vfr = ((lane >> 3) & 1) * 8 + (lane & 7);
    const int vfc = ((lane >> 4) & 1) * 8;

    float o[2][8][4];
#pragma unroll
    for (int mt = 0; mt < 2; mt++)
#pragma unroll
        for (int nb = 0; nb < 8; nb++)
#pragma unroll
            for (int j = 0; j < 4; j++) o[mt][nb][j] = 0.f;
    float mrow[2][2] = {{-1e30f, -1e30f}, {-1e30f, -1e30f}};
    float lrow[2][2] = {{0.f, 0.f}, {0.f, 0.f}};

    uint32_t qa[2][4][4];
    const int kstart = (c == 0) ? 256 : 0;
    const int ntiles = (512 - kstart) >> 6;
    bool qloaded = false;

    const int lrow_st = tid >> 2;          // 0..63
    const int cq = (tid & 3) * 2;          // chunk 0,2,4,6
    const int kvbase_tok = b * 4096 + (c - 1) * 256 + kstart;

    // prologue: KV tile 0 into stage 0 (same group as Q)
    {
        const __half* kp = qkv + (size_t)(kvbase_tok + lrow_st) * 3072 + 1024 + h * 64;
        const __half* vp = kp + 1024;
        const uint32_t kd = sKV0 + lrow_st * (AQ_STRIDE * 2);
        const uint32_t vd = kd + 64 * (AQ_STRIDE * 2);
        cp16(kd + cq * 16,       kp + cq * 8);
        cp16(kd + (cq + 1) * 16, kp + (cq + 1) * 8);
        cp16(vd + cq * 16,       vp + cq * 8);
        cp16(vd + (cq + 1) * 16, vp + (cq + 1) * 8);
        cp_commit();
    }

    for (int it = 0; it < ntiles; it++) {
        cp_wait0();
        __syncthreads();

        if (!qloaded) {
            qloaded = true;
#pragma unroll
            for (int mt = 0; mt < 2; mt++)
#pragma unroll
                for (int kk = 0; kk < 4; kk++)
                    LDSM_X4(qa[mt][kk],
                            sQ + (qfr + mt * 16) * (AQ_STRIDE * 2) + (kk * 16 + qfc) * 2);
        }

        // issue KV loads for tile it+1 into the other stage
        if (it + 1 < ntiles) {
            const int tok = kvbase_tok + (it + 1) * 64 + lrow_st;
            const __half* kp = qkv + (size_t)tok * 3072 + 1024 + h * 64;
            const __half* vp = kp + 1024;
            const uint32_t kd = sKV0 + ((it + 1) & 1) * (KV_STG * 2) + lrow_st * (AQ_STRIDE * 2);
            const uint32_t vd = kd + 64 * (AQ_STRIDE * 2);
            cp16(kd + cq * 16,       kp + cq * 8);
            cp16(kd + (cq + 1) * 16, kp + (cq + 1) * 8);
            cp16(vd + cq * 16,       vp + cq * 8);
            cp16(vd + (cq + 1) * 16, vp + (cq + 1) * 8);
            cp_commit();
        }

        const uint32_t sK = sKV0 + (it & 1) * (KV_STG * 2);
        const uint32_t sV = sK + 64 * (AQ_STRIDE * 2);

        float s[2][8][4];
#pragma unroll
        for (int mt = 0; mt < 2; mt++)
#pragma unroll
            for (int nt = 0; nt < 8; nt++)
#pragma unroll
                for (int j = 0; j < 4; j++) s[mt][nt][j] = 0.f;

#pragma unroll
        for (int kk = 0; kk < 4; kk++) {
            uint32_t kb[4][4];
#pragma unroll
            for (int ntp = 0; ntp < 4; ntp++)
                LDSM_X4(kb[ntp],
                        sK + (ntp * 16 + kfr) * (AQ_STRIDE * 2) + (kk * 16 + kfc) * 2);
#pragma unroll
            for (int mt = 0; mt < 2; mt++)
#pragma unroll
                for (int nt = 0; nt < 8; nt++)
                    mma_f16(s[mt][nt], qa[mt][kk], &kb[nt >> 1][(nt & 1) * 2]);
        }
#pragma unroll
        for (int mt = 0; mt < 2; mt++)
#pragma unroll
            for (int nt = 0; nt < 8; nt++)
#pragma unroll
                for (int j = 0; j < 4; j++) s[mt][nt][j] *= 0.125f;

#pragma unroll
        for (int mt = 0; mt < 2; mt++) {
#pragma unroll
            for (int r = 0; r < 2; r++) {
                float mx = -1e30f;
#pragma unroll
                for (int nt = 0; nt < 8; nt++)
                    mx = fmaxf(mx, fmaxf(s[mt][nt][2 * r], s[mt][nt][2 * r + 1]));
                mx = fmaxf(mx, __shfl_xor_sync(0xffffffffu, mx, 1));
                mx = fmaxf(mx, __shfl_xor_sync(0xffffffffu, mx, 2));
                const float mnew = fmaxf(mrow[mt][r], mx);
                const float corr = __expf(mrow[mt][r] - mnew);
                mrow[mt][r] = mnew;
                float ps = 0.f;
#pragma unroll
                for (int nt = 0; nt < 8; nt++) {
                    const float p0 = __expf(s[mt][nt][2 * r] - mnew);
                    const float p1 = __expf(s[mt][nt][2 * r + 1] - mnew);
                    s[mt][nt][2 * r] = p0;
                    s[mt][nt][2 * r + 1] = p1;
                    ps += p0 + p1;
                }
                lrow[mt][r] = lrow[mt][r] * corr + ps;
#pragma unroll
                for (int nb = 0; nb < 8; nb++) {
                    o[mt][nb][2 * r]     *= corr;
                    o[mt][nb][2 * r + 1] *= corr;
                }
            }
        }

#pragma unroll
        for (int j = 0; j < 4; j++) {
            uint32_t pa[2][4];
#pragma unroll
            for (int mt = 0; mt < 2; mt++) {
                pa[mt][0] = packh2(s[mt][2 * j][0], s[mt][2 * j][1]);
                pa[mt][1] = packh2(s[mt][2 * j][2], s[mt][2 * j][3]);
                pa[mt][2] = packh2(s[mt][2 * j + 1][0], s[mt][2 * j + 1][1]);
                pa[mt][3] = packh2(s[mt][2 * j + 1][2], s[mt][2 * j + 1][3]);
            }
            uint32_t vb[4][4];
#pragma unroll
            for (int nbp = 0; nbp < 4; nbp++)
                LDSM_X4_T(vb[nbp],
                          sV + (j * 16 + vfr) * (AQ_STRIDE * 2) + (nbp * 16 + vfc) * 2);
#pragma unroll
            for (int mt = 0; mt < 2; mt++)
#pragma unroll
                for (int nb = 0; nb < 8; nb++)
                    mma_f16(o[mt][nb], pa[mt], &vb[nb >> 1][(nb & 1) * 2]);
        }
    }

#pragma unroll
    for (int mt = 0; mt < 2; mt++) {
#pragma unroll
        for (int r = 0; r < 2; r++) {
            float lt = lrow[mt][r];
            lt += __shfl_xor_sync(0xffffffffu, lt, 1);
            lt += __shfl_xor_sync(0xffffffffu, lt, 2);
            const float inv = 1.f / lt;
            const int qrow = q0 + mt * 16 + r * 8 + g;
            const size_t qtok = (size_t)b * 4096 + (size_t)c * 256 + qrow;
            __half* op = out + qtok * 1024 + h * 64 + 2 * t;
#pragma unroll
            for (int nb = 0; nb < 8; nb++)
                *(__half2*)(op + nb * 8) =
                    __floats2half2_rn(o[mt][nb][2 * r] * inv, o[mt][nb][2 * r + 1] * inv);
        }
    }
}

// ======================= fused residual(+fp16) + LayerNorm =======================
__global__ __launch_bounds__(256)
void ln_kernel(const float* __restrict__ A, const __half* __restrict__ Rh,
               const float* __restrict__ gamma, const float* __restrict__ beta,
               float* __restrict__ out, __half* __restrict__ outh)
{
    const int row = blockIdx.x;
    const int tid = threadIdx.x;
    const size_t base = (size_t)row * 1024 + tid * 4;

    float4 a = *(const float4*)(A + base);
    const uint2 rr = *(const uint2*)(Rh + base);
    const float2 r01 = __half22float2(*(const __half2*)&rr.x);
    const float2 r23 = __half22float2(*(const __half2*)&rr.y);
    const float v0 = a.x + r01.x, v1 = a.y + r01.y;
    const float v2 = a.z + r23.x, v3 = a.w + r23.y;

    float s  = v0 + v1 + v2 + v3;
    float sq = v0 * v0 + v1 * v1 + v2 * v2 + v3 * v3;
#pragma unroll
    for (int off = 16; off; off >>= 1) {
        s  += __shfl_xor_sync(0xffffffffu, s,  off);
        sq += __shfl_xor_sync(0xffffffffu, sq, off);
    }
    __shared__ float ss[8], ssq[8];
    if ((tid & 31) == 0) { ss[tid >> 5] = s; ssq[tid >> 5] = sq; }
    __syncthreads();
    float S = 0.f, SQ = 0.f;
#pragma unroll
    for (int w = 0; w < 8; w++) { S += ss[w]; SQ += ssq[w]; }

    const float mean = S * (1.f / 1024.f);
    const float var  = SQ * (1.f / 1024.f) - mean * mean;
    const float inv  = rsqrtf(var + 1e-6f);

    float4 gm = *(const float4*)(gamma + tid * 4);
    float4 be = *(const float4*)(beta + tid * 4);
    float4 o;
    o.x = gm.x * (v0 - mean) * inv + be.x;
    o.y = gm.y * (v1 - mean) * inv + be.y;
    o.z = gm.z * (v2 - mean) * inv + be.z;
    o.w = gm.w * (v3 - mean) * inv + be.w;
    *(float4*)(out + base) = o;
    if (outh) {
        uint2 st;
        st.x = packh2(o.x, o.y);
        st.y = packh2(o.z, o.w);
        *(uint2*)(outh + base) = st;
    }
}

// ======================================================================
extern "C" void kernel_launch(void* const* d_in, const int* in_sizes, int n_in,
                              void* d_out, int out_size)
{
    const float* x    = (const float*)d_in[0];
    const float* inw  = (const float*)d_in[1];   // [3072,1024]
    const float* inb  = (const float*)d_in[2];
    const float* outw = (const float*)d_in[3];   // [1024,1024]
    const float* outb = (const float*)d_in[4];
    const float* g1   = (const float*)d_in[5];
    const float* b1   = (const float*)d_in[6];
    const float* w1   = (const float*)d_in[7];   // [1024,4096]
    const float* bf1  = (const float*)d_in[8];
    const float* w2   = (const float*)d_in[9];   // [4096,1024]
    const float* bf2  = (const float*)d_in[10];
    const float* g2   = (const float*)d_in[11];
    const float* b2   = (const float*)d_in[12];
    float* out = (float*)d_out;

    __half *qkvh, *xh, *attnh, *x1h, *ffnh, *tmph, *inwh, *outwh, *w1th, *w2th;
    float *x1;
    cudaGetSymbolAddress((void**)&qkvh,  g_qkvh);
    cudaGetSymbolAddress((void**)&xh,    g_xh);
    cudaGetSymbolAddress((void**)&attnh, g_attnh);
    cudaGetSymbolAddress((void**)&x1h,   g_x1h);
    cudaGetSymbolAddress((void**)&ffnh,  g_ffnh);
    cudaGetSymbolAddress((void**)&tmph,  g_tmph);
    cudaGetSymbolAddress((void**)&inwh,  g_inwh);
    cudaGetSymbolAddress((void**)&outwh, g_outwh);
    cudaGetSymbolAddress((void**)&w1th,  g_w1th);
    cudaGetSymbolAddress((void**)&w2th,  g_w2th);
    cudaGetSymbolAddress((void**)&x1,    g_x1);

    cudaFuncSetAttribute(hgemm_kernel<false, true>,
                         cudaFuncAttributeMaxDynamicSharedMemorySize, GEMM_SMEM);
    cudaFuncSetAttribute(hgemm_kernel<true, true>,
                         cudaFuncAttributeMaxDynamicSharedMemorySize, GEMM_SMEM);
    cudaFuncSetAttribute(attn_kernel,
                         cudaFuncAttributeMaxDynamicSharedMemorySize, ATTN_SMEM);

    const dim3 blk(256);
    const dim3 gblk(512);

    // ---- one-time conversions ----
    cvt_kernel<<<8192, blk>>>(x,    xh,    16384ull * 1024 / 8);
    cvt_kernel<<<1536, blk>>>(inw,  inwh,  3072ull * 1024 / 8);
    cvt_kernel<<<512,  blk>>>(outw, outwh, 1024ull * 1024 / 8);
    transpose_cvt_kernel<<<dim3(128, 32), dim3(32, 8)>>>(w1, w1th, 1024, 4096);
    transpose_cvt_kernel<<<dim3(32, 128), dim3(32, 8)>>>(w2, w2th, 4096, 1024);

    // qkv = x @ in_proj_w^T + b   -> fp16 [16384,3072]
    hgemm_kernel<false, true><<<dim3(12, 128), gblk, GEMM_SMEM>>>(xh, inwh, inb, qkvh, 3072, 1024);
    // windowed attention          -> fp16 [16384,1024]
    attn_kernel<<<1024, blk, ATTN_SMEM>>>(qkvh, attnh);
    // attn_out = attn @ out_w^T + b -> fp16 tmph
    hgemm_kernel<false, true><<<dim3(4, 128), gblk, GEMM_SMEM>>>(attnh, outwh, outb, tmph, 1024, 1024);
    // x1 = LN(x + attn_out)  (fp32 + fp16 copy)
    ln_kernel<<<16384, blk>>>(x, tmph, g1, b1, x1, x1h);
    // h = relu(x1 @ w1 + bf1) -> fp16 [16384,4096]
    hgemm_kernel<true, true><<<dim3(16, 128), gblk, GEMM_SMEM>>>(x1h, w1th, bf1, ffnh, 4096, 1024);
    // y = h @ w2 + bf2 -> fp16 tmph
    hgemm_kernel<false, true><<<dim3(4, 128), gblk, GEMM_SMEM>>>(ffnh, w2th, bf2, tmph, 1024, 4096);
    // out = LN(x1 + y)
    ln_kernel<<<16384, blk>>>(x1, tmph, g2, b2, out, (__half*)0);
}

// round 13
// speedup vs baseline: 1.0691x; 1.0691x over previous
#include <cuda_runtime.h>
#include <cuda_fp16.h>
#include <math.h>
#include <stdint.h>

// B=4, L=4096, D=1024, H=16, W=256, FF=4096, HD=64, nC=16, M=B*L=16384

// -------- scratch (device globals; no allocation allowed) --------
__device__ __half g_qkvh [16384ull * 3072];
__device__ __half g_xh   [16384ull * 1024];
__device__ __half g_attnh[16384ull * 1024];
__device__ __half g_x1h  [16384ull * 1024];
__device__ __half g_ffnh [16384ull * 4096];
__device__ __half g_tmph [16384ull * 1024];
__device__ __half g_inwh [3072ull * 1024];
__device__ __half g_outwh[1024ull * 1024];
__device__ __half g_w1th [4096ull * 1024];
__device__ __half g_w2th [1024ull * 4096];
__device__ float  g_x1   [16384ull * 1024];

// ======================= helpers =======================
__device__ __forceinline__ uint32_t smem_u32(const void* p) {
    uint32_t a;
    asm("{ .reg .u64 t; cvta.to.shared.u64 t, %1; cvt.u32.u64 %0, t; }"
        : "=r"(a) : "l"(p));
    return a;
}
__device__ __forceinline__ void cp16(uint32_t saddr, const void* g) {
    asm volatile("cp.async.cg.shared.global [%0], [%1], 16;"
                 :: "r"(saddr), "l"(g) : "memory");
}
__device__ __forceinline__ void cp_commit() {
    asm volatile("cp.async.commit_group;" ::: "memory");
}
__device__ __forceinline__ void cp_wait1() {
    asm volatile("cp.async.wait_group 1;" ::: "memory");
}
__device__ __forceinline__ void cp_wait0() {
    asm volatile("cp.async.wait_group 0;" ::: "memory");
}
__device__ __forceinline__ void mma_f16(float* c, const uint32_t* a, const uint32_t* b) {
    asm volatile(
        "mma.sync.aligned.m16n8k16.row.col.f32.f16.f16.f32 "
        "{%0,%1,%2,%3},{%4,%5,%6,%7},{%8,%9},{%0,%1,%2,%3};"
        : "+f"(c[0]), "+f"(c[1]), "+f"(c[2]), "+f"(c[3])
        : "r"(a[0]), "r"(a[1]), "r"(a[2]), "r"(a[3]), "r"(b[0]), "r"(b[1]));
}
#define LDSM_X4(R, addr) \
    asm volatile("ldmatrix.sync.aligned.m8n8.x4.shared.b16 {%0,%1,%2,%3}, [%4];" \
                 : "=r"((R)[0]), "=r"((R)[1]), "=r"((R)[2]), "=r"((R)[3]) : "r"(addr))
#define LDSM_X4_T(R, addr) \
    asm volatile("ldmatrix.sync.aligned.m8n8.x4.trans.shared.b16 {%0,%1,%2,%3}, [%4];" \
                 : "=r"((R)[0]), "=r"((R)[1]), "=r"((R)[2]), "=r"((R)[3]) : "r"(addr))
__device__ __forceinline__ uint32_t packh2(float a, float b) {
    __half2 h = __floats2half2_rn(a, b);
    return *(uint32_t*)&h;
}

// ======================= fp16 mma.sync GEMM (R11 winner, unchanged) =======================
// C[M,N] = Ah[M,K] @ Bth[N,K]^T + bias (optional ReLU, optional fp16 out).
// CTA tile 128x128, BK=64, 8 warps (2M x 4N), warp tile 64x32.
// 3-stage cp.async; XOR chunk swizzle (chunk ^= row&7).
// ONE barrier per iter, issue-after-sync. 2 CTAs/SM (96KB smem, ~natural regs).

#define STG_BYTES 32768            // A(16384) + B(16384) per stage
#define GEMM_SMEM (3 * STG_BYTES)  // 98304

template<bool RELU, bool OUTH>
__global__ __launch_bounds__(256)
void hgemm_kernel(const __half* __restrict__ A, const __half* __restrict__ Bt,
                  const float* __restrict__ bias, void* __restrict__ Cv,
                  int N, int K)
{
    extern __shared__ __align__(128) char smem[];
    const uint32_t sb = smem_u32(smem);

    const int tid  = threadIdx.x;
    const int lane = tid & 31;
    const int wid  = tid >> 5;
    const int g = lane >> 2;
    const int t = lane & 3;
    const int wm = (wid & 1) * 64;
    const int wn = (wid >> 1) * 32;

    const int bm = blockIdx.y * 128;
    const int bn = blockIdx.x * 128;

    const int srow = tid >> 1;
    const int scc0 = (tid & 1) * 4;
    const int sswz = srow & 7;
    const __half* Ag = A  + (size_t)(bm + srow) * K + scc0 * 8;
    const __half* Bg = Bt + (size_t)(bn + srow) * K + scc0 * 8;
    uint32_t dstA[4], dstB[4];
#pragma unroll
    for (int i = 0; i < 4; i++) {
        const uint32_t off = srow * 128 + (((scc0 + i) ^ sswz) << 4);
        dstA[i] = sb + off;
        dstB[i] = sb + 16384 + off;
    }

    const int KT = K >> 6;

#pragma unroll
    for (int s = 0; s < 2; s++) {
        const uint32_t off = s * STG_BYTES;
        const int k0 = s * 64;
#pragma unroll
        for (int i = 0; i < 4; i++) {
            cp16(dstA[i] + off, Ag + k0 + i * 8);
            cp16(dstB[i] + off, Bg + k0 + i * 8);
        }
        cp_commit();
    }

    float c[16][4];
#pragma unroll
    for (int i = 0; i < 16; i++)
#pragma unroll
        for (int j = 0; j < 4; j++) c[i][j] = 0.f;

    const int afr = wm + (lane & 15);
    const int a8  = lane >> 4;
    const int bfr = wn + ((lane >> 4) & 1) * 8 + (lane & 7);
    const int b8  = (lane >> 3) & 1;
    const int fswz = lane & 7;

    int rd = 0, wr = 2;
    for (int kt = 0; kt < KT; kt++) {
        cp_wait1();
        __syncthreads();

        if (kt + 2 < KT) {
            const uint32_t off = wr * STG_BYTES;
            const int k0 = (kt + 2) * 64;
#pragma unroll
            for (int i = 0; i < 4; i++) {
                cp16(dstA[i] + off, Ag + k0 + i * 8);
                cp16(dstB[i] + off, Bg + k0 + i * 8);
            }
            cp_commit();
        }
        wr = (wr == 2) ? 0 : wr + 1;

        const uint32_t sA = sb + rd * STG_BYTES;
        const uint32_t sB = sA + 16384;
        rd = (rd == 2) ? 0 : rd + 1;

#pragma unroll
        for (int kk = 0; kk < 4; kk++) {
            uint32_t a[4][4], kb[2][4];
            const int ca = ((kk * 2 + a8) ^ fswz) << 4;
            const int cb = ((kk * 2 + b8) ^ fswz) << 4;
#pragma unroll
            for (int mt = 0; mt < 4; mt++)
                LDSM_X4(a[mt], sA + (afr + mt * 16) * 128 + ca);
#pragma unroll
            for (int ntp = 0; ntp < 2; ntp++)
                LDSM_X4(kb[ntp], sB + (bfr + ntp * 16) * 128 + cb);
#pragma unroll
            for (int mt = 0; mt < 4; mt++)
#pragma unroll
                for (int nt = 0; nt < 4; nt++)
                    mma_f16(c[mt * 4 + nt], a[mt], &kb[nt >> 1][(nt & 1) * 2]);
        }
    }

    // epilogue
#pragma unroll
    for (int mt = 0; mt < 4; mt++) {
#pragma unroll
        for (int nt = 0; nt < 4; nt++) {
            const float* cc = c[mt * 4 + nt];
            const int row = bm + wm + mt * 16 + g;
            const int col = bn + wn + nt * 8 + 2 * t;
            const float bx = __ldg(bias + col);
            const float by = __ldg(bias + col + 1);
            float v00 = cc[0] + bx, v01 = cc[1] + by;
            float v10 = cc[2] + bx, v11 = cc[3] + by;
            if (RELU) {
                v00 = fmaxf(v00, 0.f); v01 = fmaxf(v01, 0.f);
                v10 = fmaxf(v10, 0.f); v11 = fmaxf(v11, 0.f);
            }
            if (OUTH) {
                __half* C = (__half*)Cv;
                *(__half2*)(C + (size_t)row * N + col)       = __floats2half2_rn(v00, v01);
                *(__half2*)(C + (size_t)(row + 8) * N + col) = __floats2half2_rn(v10, v11);
            } else {
                float* C = (float*)Cv;
                float2 a0; a0.x = v00; a0.y = v01;
                float2 a1; a1.x = v10; a1.y = v11;
                *(float2*)(C + (size_t)row * N + col)       = a0;
                *(float2*)(C + (size_t)(row + 8) * N + col) = a1;
            }
        }
    }
}

// ======================= converters =======================
__global__ __launch_bounds__(256)
void cvt_kernel(const float* __restrict__ in, __half* __restrict__ out, size_t n8)
{
    const size_t i = (size_t)blockIdx.x * 256 + threadIdx.x;
    if (i >= n8) return;
    const float4 u = *(const float4*)(in + i * 8);
    const float4 v = *(const float4*)(in + i * 8 + 4);
    uint4 st;
    st.x = packh2(u.x, u.y); st.y = packh2(u.z, u.w);
    st.z = packh2(v.x, v.y); st.w = packh2(v.z, v.w);
    *(uint4*)(out + i * 8) = st;
}

__global__ __launch_bounds__(256)
void transpose_cvt_kernel(const float* __restrict__ in, __half* __restrict__ out,
                          int R, int C)  // in[R,C] fp32 -> out[C,R] fp16
{
    __shared__ float tbuf[32][33];
    const int tx = threadIdx.x, ty = threadIdx.y;
    const int x = blockIdx.x * 32 + tx;
    const int y0 = blockIdx.y * 32;
#pragma unroll
    for (int j = ty; j < 32; j += 8)
        tbuf[j][tx] = in[(size_t)(y0 + j) * C + x];
    __syncthreads();
    const int ox = y0 + tx;
    const int oy0 = blockIdx.x * 32;
#pragma unroll
    for (int j = ty; j < 32; j += 8)
        out[(size_t)(oy0 + j) * R + ox] = __float2half(tbuf[tx][j]);
}

// ======================= fp16 tensor-core windowed attention =======================
// Double-buffered K/V stages (R12 version, kept for isolation testing).
#define AQ_STRIDE 72
#define KV_STG (128 * AQ_STRIDE)                       // K(64 rows)+V(64 rows) halves
#define ATTN_SMEM ((256 * AQ_STRIDE + 2 * KV_STG) * 2) // 73728 B

__global__ __launch_bounds__(256, 1)
void attn_kernel(const __half* __restrict__ qkv, __half* __restrict__ out)
{
    extern __shared__ __align__(128) char asmem[];
    const uint32_t sQ = smem_u32(asmem);
    const uint32_t sKV0 = sQ + 256 * AQ_STRIDE * 2;

    const int idx = blockIdx.x;        // b*256 + c*16 + h
    const int h = idx & 15;
    const int c = (idx >> 4) & 15;
    const int b = idx >> 8;
    const int tid = threadIdx.x;
    const int lane = tid & 31;
    const int wid = tid >> 5;
    const int g = lane >> 2;
    const int t = lane & 3;
    const int q0 = wid * 32;

    // ---- stage Q via cp.async ----
    {
        const size_t qtok = (size_t)b * 4096 + (size_t)c * 256 + tid;
        const __half* qp = qkv + qtok * 3072 + h * 64;
        const uint32_t dst = sQ + tid * (AQ_STRIDE * 2);
#pragma unroll
        for (int i = 0; i < 8; i++)
            cp16(dst + i * 16, qp + i * 8);
    }

    const int qfr = q0 + (lane & 15);
    const int qfc = (lane >> 4) * 8;
    const int kfr = ((lane >> 4) & 1) * 8 + (lane & 7);
    const int kfc = ((lane >> 3) & 1) * 8;
    const int vfr = ((lane >> 3) & 1) * 8 + (lane & 7);
    const int vfc = ((lane >> 4) & 1) * 8;

    float o[2][8][4];
#pragma unroll
    for (int mt = 0; mt < 2; mt++)
#pragma unroll
        for (int nb = 0; nb < 8; nb++)
#pragma unroll
            for (int j = 0; j < 4; j++) o[mt][nb][j] = 0.f;
    float mrow[2][2] = {{-1e30f, -1e30f}, {-1e30f, -1e30f}};
    float lrow[2][2] = {{0.f, 0.f}, {0.f, 0.f}};

    uint32_t qa[2][4][4];
    const int kstart = (c == 0) ? 256 : 0;
    const int ntiles = (512 - kstart) >> 6;
    bool qloaded = false;

    const int lrow_st = tid >> 2;          // 0..63
    const int cq = (tid & 3) * 2;          // chunk 0,2,4,6
    const int kvbase_tok = b * 4096 + (c - 1) * 256 + kstart;

    // prologue: KV tile 0 into stage 0 (same group as Q)
    {
        const __half* kp = qkv + (size_t)(kvbase_tok + lrow_st) * 3072 + 1024 + h * 64;
        const __half* vp = kp + 1024;
        const uint32_t kd = sKV0 + lrow_st * (AQ_STRIDE * 2);
        const uint32_t vd = kd + 64 * (AQ_STRIDE * 2);
        cp16(kd + cq * 16,       kp + cq * 8);
        cp16(kd + (cq + 1) * 16, kp + (cq + 1) * 8);
        cp16(vd + cq * 16,       vp + cq * 8);
        cp16(vd + (cq + 1) * 16, vp + (cq + 1) * 8);
        cp_commit();
    }

    for (int it = 0; it < ntiles; it++) {
        cp_wait0();
        __syncthreads();

        if (!qloaded) {
            qloaded = true;
#pragma unroll
            for (int mt = 0; mt < 2; mt++)
#pragma unroll
                for (int kk = 0; kk < 4; kk++)
                    LDSM_X4(qa[mt][kk],
                            sQ + (qfr + mt * 16) * (AQ_STRIDE * 2) + (kk * 16 + qfc) * 2);
        }

        // issue KV loads for tile it+1 into the other stage
        if (it + 1 < ntiles) {
            const int tok = kvbase_tok + (it + 1) * 64 + lrow_st;
            const __half* kp = qkv + (size_t)tok * 3072 + 1024 + h * 64;
            const __half* vp = kp + 1024;
            const uint32_t kd = sKV0 + ((it + 1) & 1) * (KV_STG * 2) + lrow_st * (AQ_STRIDE * 2);
            const uint32_t vd = kd + 64 * (AQ_STRIDE * 2);
            cp16(kd + cq * 16,       kp + cq * 8);
            cp16(kd + (cq + 1) * 16, kp + (cq + 1) * 8);
            cp16(vd + cq * 16,       vp + cq * 8);
            cp16(vd + (cq + 1) * 16, vp + (cq + 1) * 8);
            cp_commit();
        }

        const uint32_t sK = sKV0 + (it & 1) * (KV_STG * 2);
        const uint32_t sV = sK + 64 * (AQ_STRIDE * 2);

        float s[2][8][4];
#pragma unroll
        for (int mt = 0; mt < 2; mt++)
#pragma unroll
            for (int nt = 0; nt < 8; nt++)
#pragma unroll
                for (int j = 0; j < 4; j++) s[mt][nt][j] = 0.f;

#pragma unroll
        for (int kk = 0; kk < 4; kk++) {
            uint32_t kb[4][4];
#pragma unroll
            for (int ntp = 0; ntp < 4; ntp++)
                LDSM_X4(kb[ntp],
                        sK + (ntp * 16 + kfr) * (AQ_STRIDE * 2) + (kk * 16 + kfc) * 2);
#pragma unroll
            for (int mt = 0; mt < 2; mt++)
#pragma unroll
                for (int nt = 0; nt < 8; nt++)
                    mma_f16(s[mt][nt], qa[mt][kk], &kb[nt >> 1][(nt & 1) * 2]);
        }
#pragma unroll
        for (int mt = 0; mt < 2; mt++)
#pragma unroll
            for (int nt = 0; nt < 8; nt++)
#pragma unroll
                for (int j = 0; j < 4; j++) s[mt][nt][j] *= 0.125f;

#pragma unroll
        for (int mt = 0; mt < 2; mt++) {
#pragma unroll
            for (int r = 0; r < 2; r++) {
                float mx = -1e30f;
#pragma unroll
                for (int nt = 0; nt < 8; nt++)
                    mx = fmaxf(mx, fmaxf(s[mt][nt][2 * r], s[mt][nt][2 * r + 1]));
                mx = fmaxf(mx, __shfl_xor_sync(0xffffffffu, mx, 1));
                mx = fmaxf(mx, __shfl_xor_sync(0xffffffffu, mx, 2));
                const float mnew = fmaxf(mrow[mt][r], mx);
                const float corr = __expf(mrow[mt][r] - mnew);
                mrow[mt][r] = mnew;
                float ps = 0.f;
#pragma unroll
                for (int nt = 0; nt < 8; nt++) {
                    const float p0 = __expf(s[mt][nt][2 * r] - mnew);
                    const float p1 = __expf(s[mt][nt][2 * r + 1] - mnew);
                    s[mt][nt][2 * r] = p0;
                    s[mt][nt][2 * r + 1] = p1;
                    ps += p0 + p1;
                }
                lrow[mt][r] = lrow[mt][r] * corr + ps;
#pragma unroll
                for (int nb = 0; nb < 8; nb++) {
                    o[mt][nb][2 * r]     *= corr;
                    o[mt][nb][2 * r + 1] *= corr;
                }
            }
        }

#pragma unroll
        for (int j = 0; j < 4; j++) {
            uint32_t pa[2][4];
#pragma unroll
            for (int mt = 0; mt < 2; mt++) {
                pa[mt][0] = packh2(s[mt][2 * j][0], s[mt][2 * j][1]);
                pa[mt][1] = packh2(s[mt][2 * j][2], s[mt][2 * j][3]);
                pa[mt][2] = packh2(s[mt][2 * j + 1][0], s[mt][2 * j + 1][1]);
                pa[mt][3] = packh2(s[mt][2 * j + 1][2], s[mt][2 * j + 1][3]);
            }
            uint32_t vb[4][4];
#pragma unroll
            for (int nbp = 0; nbp < 4; nbp++)
                LDSM_X4_T(vb[nbp],
                          sV + (j * 16 + vfr) * (AQ_STRIDE * 2) + (nbp * 16 + vfc) * 2);
#pragma unroll
            for (int mt = 0; mt < 2; mt++)
#pragma unroll
                for (int nb = 0; nb < 8; nb++)
                    mma_f16(o[mt][nb], pa[mt], &vb[nb >> 1][(nb & 1) * 2]);
        }
    }

#pragma unroll
    for (int mt = 0; mt < 2; mt++) {
#pragma unroll
        for (int r = 0; r < 2; r++) {
            float lt = lrow[mt][r];
            lt += __shfl_xor_sync(0xffffffffu, lt, 1);
            lt += __shfl_xor_sync(0xffffffffu, lt, 2);
            const float inv = 1.f / lt;
            const int qrow = q0 + mt * 16 + r * 8 + g;
            const size_t qtok = (size_t)b * 4096 + (size_t)c * 256 + qrow;
            __half* op = out + qtok * 1024 + h * 64 + 2 * t;
#pragma unroll
            for (int nb = 0; nb < 8; nb++)
                *(__half2*)(op + nb * 8) =
                    __floats2half2_rn(o[mt][nb][2 * r] * inv, o[mt][nb][2 * r + 1] * inv);
        }
    }
}

// ======================= fused residual(+fp16) + LayerNorm =======================
__global__ __launch_bounds__(256)
void ln_kernel(const float* __restrict__ A, const __half* __restrict__ Rh,
               const float* __restrict__ gamma, const float* __restrict__ beta,
               float* __restrict__ out, __half* __restrict__ outh)
{
    const int row = blockIdx.x;
    const int tid = threadIdx.x;
    const size_t base = (size_t)row * 1024 + tid * 4;

    float4 a = *(const float4*)(A + base);
    const uint2 rr = *(const uint2*)(Rh + base);
    const float2 r01 = __half22float2(*(const __half2*)&rr.x);
    const float2 r23 = __half22float2(*(const __half2*)&rr.y);
    const float v0 = a.x + r01.x, v1 = a.y + r01.y;
    const float v2 = a.z + r23.x, v3 = a.w + r23.y;

    float s  = v0 + v1 + v2 + v3;
    float sq = v0 * v0 + v1 * v1 + v2 * v2 + v3 * v3;
#pragma unroll
    for (int off = 16; off; off >>= 1) {
        s  += __shfl_xor_sync(0xffffffffu, s,  off);
        sq += __shfl_xor_sync(0xffffffffu, sq, off);
    }
    __shared__ float ss[8], ssq[8];
    if ((tid & 31) == 0) { ss[tid >> 5] = s; ssq[tid >> 5] = sq; }
    __syncthreads();
    float S = 0.f, SQ = 0.f;
#pragma unroll
    for (int w = 0; w < 8; w++) { S += ss[w]; SQ += ssq[w]; }

    const float mean = S * (1.f / 1024.f);
    const float var  = SQ * (1.f / 1024.f) - mean * mean;
    const float inv  = rsqrtf(var + 1e-6f);

    float4 gm = *(const float4*)(gamma + tid * 4);
    float4 be = *(const float4*)(beta + tid * 4);
    float4 o;
    o.x = gm.x * (v0 - mean) * inv + be.x;
    o.y = gm.y * (v1 - mean) * inv + be.y;
    o.z = gm.z * (v2 - mean) * inv + be.z;
    o.w = gm.w * (v3 - mean) * inv + be.w;
    *(float4*)(out + base) = o;
    if (outh) {
        uint2 st;
        st.x = packh2(o.x, o.y);
        st.y = packh2(o.z, o.w);
        *(uint2*)(outh + base) = st;
    }
}

// ======================================================================
extern "C" void kernel_launch(void* const* d_in, const int* in_sizes, int n_in,
                              void* d_out, int out_size)
{
    const float* x    = (const float*)d_in[0];
    const float* inw  = (const float*)d_in[1];   // [3072,1024]
    const float* inb  = (const float*)d_in[2];
    const float* outw = (const float*)d_in[3];   // [1024,1024]
    const float* outb = (const float*)d_in[4];
    const float* g1   = (const float*)d_in[5];
    const float* b1   = (const float*)d_in[6];
    const float* w1   = (const float*)d_in[7];   // [1024,4096]
    const float* bf1  = (const float*)d_in[8];
    const float* w2   = (const float*)d_in[9];   // [4096,1024]
    const float* bf2  = (const float*)d_in[10];
    const float* g2   = (const float*)d_in[11];
    const float* b2   = (const float*)d_in[12];
    float* out = (float*)d_out;

    __half *qkvh, *xh, *attnh, *x1h, *ffnh, *tmph, *inwh, *outwh, *w1th, *w2th;
    float *x1;
    cudaGetSymbolAddress((void**)&qkvh,  g_qkvh);
    cudaGetSymbolAddress((void**)&xh,    g_xh);
    cudaGetSymbolAddress((void**)&attnh, g_attnh);
    cudaGetSymbolAddress((void**)&x1h,   g_x1h);
    cudaGetSymbolAddress((void**)&ffnh,  g_ffnh);
    cudaGetSymbolAddress((void**)&tmph,  g_tmph);
    cudaGetSymbolAddress((void**)&inwh,  g_inwh);
    cudaGetSymbolAddress((void**)&outwh, g_outwh);
    cudaGetSymbolAddress((void**)&w1th,  g_w1th);
    cudaGetSymbolAddress((void**)&w2th,  g_w2th);
    cudaGetSymbolAddress((void**)&x1,    g_x1);

    cudaFuncSetAttribute(hgemm_kernel<false, true>,
                         cudaFuncAttributeMaxDynamicSharedMemorySize, GEMM_SMEM);
    cudaFuncSetAttribute(hgemm_kernel<true, true>,
                         cudaFuncAttributeMaxDynamicSharedMemorySize, GEMM_SMEM);
    cudaFuncSetAttribute(attn_kernel,
                         cudaFuncAttributeMaxDynamicSharedMemorySize, ATTN_SMEM);

    const dim3 blk(256);

    // ---- one-time conversions ----
    cvt_kernel<<<8192, blk>>>(x,    xh,    16384ull * 1024 / 8);
    cvt_kernel<<<1536, blk>>>(inw,  inwh,  3072ull * 1024 / 8);
    cvt_kernel<<<512,  blk>>>(outw, outwh, 1024ull * 1024 / 8);
    transpose_cvt_kernel<<<dim3(128, 32), dim3(32, 8)>>>(w1, w1th, 1024, 4096);
    transpose_cvt_kernel<<<dim3(32, 128), dim3(32, 8)>>>(w2, w2th, 4096, 1024);

    // qkv = x @ in_proj_w^T + b   -> fp16 [16384,3072]
    hgemm_kernel<false, true><<<dim3(24, 128), blk, GEMM_SMEM>>>(xh, inwh, inb, qkvh, 3072, 1024);
    // windowed attention          -> fp16 [16384,1024]
    attn_kernel<<<1024, blk, ATTN_SMEM>>>(qkvh, attnh);
    // attn_out = attn @ out_w^T + b -> fp16 tmph
    hgemm_kernel<false, true><<<dim3(8, 128), blk, GEMM_SMEM>>>(attnh, outwh, outb, tmph, 1024, 1024);
    // x1 = LN(x + attn_out)  (fp32 + fp16 copy)
    ln_kernel<<<16384, blk>>>(x, tmph, g1, b1, x1, x1h);
    // h = relu(x1 @ w1 + bf1) -> fp16 [16384,4096]
    hgemm_kernel<true, true><<<dim3(32, 128), blk, GEMM_SMEM>>>(x1h, w1th, bf1, ffnh, 4096, 1024);
    // y = h @ w2 + bf2 -> fp16 tmph
    hgemm_kernel<false, true><<<dim3(8, 128), blk, GEMM_SMEM>>>(ffnh, w2th, bf2, tmph, 1024, 4096);
    // out = LN(x1 + y)
    ln_kernel<<<16384, blk>>>(x1, tmph, g2, b2, out, (__half*)0);
}